// round 2
// baseline (speedup 1.0000x reference)
#include <cuda_runtime.h>
#include <cstdint>

#define N_NODES 50000
#define C 128
#define E_EDGES 600000

// ---------------- scratch (device globals; no runtime allocation) ----------
__device__ float g_A[N_NODES * C];        // A[dst] table (incl. ba)
__device__ float g_B[N_NODES * C];        // B[src] table; reused as gemm_out L1 scratch
__device__ float g_R[N_NODES * C];        // per-node relu-sum accumulator
__device__ float g_H[N_NODES * C];        // layer-1 normalized output
__device__ float g_deg[N_NODES];          // per-node in-degree (as float)
__device__ int   g_src[E_EDGES];
__device__ int   g_dst[E_EDGES];
__device__ int   g_is64;
__device__ float g_Wc[2][256 * C];        // rows 0..127 = WaL-WaR, 128..255 = WaR
__device__ float g_s[2][C];               // BN scale
__device__ float g_c[2][C];               // BN shift

// ---------------- edge index dtype sniff + convert -------------------------
__global__ void detect_kernel(const void* __restrict__ ei) {
    if (threadIdx.x == 0) {
        const long long* p = (const long long*)ei;
        int is64 = 1;
        for (int i = 0; i < 16; i++) {
            long long v = p[i];
            if (v < 0 || v >= (long long)N_NODES) { is64 = 0; break; }
        }
        g_is64 = is64;
    }
}

__global__ void convert_kernel(const void* __restrict__ ei) {
    int e = blockIdx.x * blockDim.x + threadIdx.x;
    if (e >= 2 * E_EDGES) return;
    int v;
    if (g_is64) v = (int)((const long long*)ei)[e];
    else        v = ((const int*)ei)[e];
    if (e < E_EDGES) g_src[e] = v;
    else             g_dst[e - E_EDGES] = v;
}

// ---------------- prep kernels ---------------------------------------------
__global__ void prep_weights(const float* __restrict__ w1a, const float* __restrict__ w2a) {
    int gid = blockIdx.x * blockDim.x + threadIdx.x;   // 2 * 256 * 128 = 65536
    if (gid >= 2 * 256 * C) return;
    int layer = gid >> 15;
    int r = (gid >> 7) & 255;
    int k = gid & 127;
    const float* wa = layer ? w2a : w1a;               // [C, 2C] row-major
    float v;
    if (r < C) v = wa[r * (2 * C) + k] - wa[r * (2 * C) + C + k];
    else       v = wa[(r - C) * (2 * C) + C + k];
    g_Wc[layer][r * C + k] = v;
}

__global__ void prep_sc(const float* g1, const float* be1, const float* rm1, const float* rv1,
                        const float* g2, const float* be2, const float* rm2, const float* rv2) {
    int t = threadIdx.x;                                // 0..255
    int layer = t >> 7;
    int k = t & 127;
    const float* g  = layer ? g2  : g1;
    const float* be = layer ? be2 : be1;
    const float* rm = layer ? rm2 : rm1;
    const float* rv = layer ? rv2 : rv1;
    float s = g[k] * rsqrtf(rv[k] + 1e-5f);
    g_s[layer][k] = s;
    g_c[layer][k] = be[k] - rm[k] * s;
}

__global__ void zero_kernel(int zero_deg) {
    int i = blockIdx.x * blockDim.x + threadIdx.x;
    if (i < N_NODES * C / 4) ((float4*)g_R)[i] = make_float4(0.f, 0.f, 0.f, 0.f);
    if (zero_deg && i < N_NODES) g_deg[i] = 0.f;
}

__global__ void deg_kernel() {
    int e = blockIdx.x * blockDim.x + threadIdx.x;
    if (e < E_EDGES) atomicAdd(&g_deg[g_dst[e]], 1.0f);
}

// ---------------- GEMM 1: [A | B] = X @ Wc^T (+ba on A half) ---------------
// blockIdx.y = 0 -> A half (with bias), 1 -> B half
__global__ __launch_bounds__(256) void gemm_ab_kernel(
    const float* __restrict__ Xin, const float* __restrict__ ba, int layer, int use_H) {
    const float* X = use_H ? g_H : Xin;
    __shared__ float As[8][132];
    __shared__ float Ws[8][132];
    int i0 = blockIdx.x * 128;
    int half = blockIdx.y;
    const float* W = &g_Wc[layer][half * (C * C)];
    float* out = half ? g_B : g_A;
    int tid = threadIdx.x;
    int tx = tid & 15, ty = tid >> 4;
    int lr = tid >> 1;
    int lk = (tid & 1) * 4;
    int gi = i0 + lr;
    const float* xrow = X + (size_t)gi * C;
    const float* wrow = W + (size_t)lr * C;
    float acc[8][8];
#pragma unroll
    for (int m = 0; m < 8; m++)
#pragma unroll
        for (int n = 0; n < 8; n++) acc[m][n] = 0.f;

    for (int k0 = 0; k0 < C; k0 += 8) {
        float4 xv = make_float4(0.f, 0.f, 0.f, 0.f);
        if (gi < N_NODES) xv = *(const float4*)(xrow + k0 + lk);
        float4 wv = *(const float4*)(wrow + k0 + lk);
        As[lk + 0][lr] = xv.x; As[lk + 1][lr] = xv.y; As[lk + 2][lr] = xv.z; As[lk + 3][lr] = xv.w;
        Ws[lk + 0][lr] = wv.x; Ws[lk + 1][lr] = wv.y; Ws[lk + 2][lr] = wv.z; Ws[lk + 3][lr] = wv.w;
        __syncthreads();
#pragma unroll
        for (int kk = 0; kk < 8; kk++) {
            float a[8], b[8];
#pragma unroll
            for (int m = 0; m < 8; m++) a[m] = As[kk][ty * 8 + m];
#pragma unroll
            for (int n = 0; n < 8; n++) b[n] = Ws[kk][tx * 8 + n];
#pragma unroll
            for (int m = 0; m < 8; m++)
#pragma unroll
                for (int n = 0; n < 8; n++) acc[m][n] = fmaf(a[m], b[n], acc[m][n]);
        }
        __syncthreads();
    }
#pragma unroll
    for (int m = 0; m < 8; m++) {
        int go = i0 + ty * 8 + m;
        if (go < N_NODES) {
#pragma unroll
            for (int n = 0; n < 8; n += 4) {
                int j = tx * 8 + n;
                float4 v;
                v.x = acc[m][n + 0] + (half == 0 ? ba[j + 0] : 0.f);
                v.y = acc[m][n + 1] + (half == 0 ? ba[j + 1] : 0.f);
                v.z = acc[m][n + 2] + (half == 0 ? ba[j + 2] : 0.f);
                v.w = acc[m][n + 3] + (half == 0 ? ba[j + 3] : 0.f);
                *(float4*)(out + (size_t)go * C + j) = v;
            }
        }
    }
}

// ---------------- edge pass: R[dst] += relu(A[dst] + B[src]) ---------------
__global__ __launch_bounds__(256) void edge_kernel() {
    int w = (blockIdx.x * blockDim.x + threadIdx.x) >> 5;
    int lane = threadIdx.x & 31;
    if (w >= E_EDGES) return;
    int src = g_src[w];
    int dst = g_dst[w];
    float4 a = *(const float4*)(g_A + (size_t)dst * C + lane * 4);
    float4 b = *(const float4*)(g_B + (size_t)src * C + lane * 4);
    float4 v;
    v.x = fmaxf(a.x + b.x, 0.f);
    v.y = fmaxf(a.y + b.y, 0.f);
    v.z = fmaxf(a.z + b.z, 0.f);
    v.w = fmaxf(a.w + b.w, 0.f);
    float* r = g_R + (size_t)dst * C + lane * 4;
    atomicAdd(r + 0, v.x);
    atomicAdd(r + 1, v.y);
    atomicAdd(r + 2, v.z);
    atomicAdd(r + 3, v.w);
}

// ------- GEMM 2: out = (s*R + deg*c) @ Wb^T + deg*bb -----------------------
__global__ __launch_bounds__(256) void gemm_out_kernel(
    const float* __restrict__ Wb, const float* __restrict__ bbias,
    int layer, float* __restrict__ dout, int to_dout) {
    __shared__ float As[8][132];
    __shared__ float Ws[8][132];
    __shared__ float s_sh[C];
    __shared__ float c_sh[C];
    int tid = threadIdx.x;
    if (tid < C) { s_sh[tid] = g_s[layer][tid]; c_sh[tid] = g_c[layer][tid]; }
    int i0 = blockIdx.x * 128;
    int tx = tid & 15, ty = tid >> 4;
    int lr = tid >> 1;
    int lk = (tid & 1) * 4;
    int gi = i0 + lr;
    float dg = (gi < N_NODES) ? g_deg[gi] : 0.f;
    float acc[8][8];
#pragma unroll
    for (int m = 0; m < 8; m++)
#pragma unroll
        for (int n = 0; n < 8; n++) acc[m][n] = 0.f;
    __syncthreads();   // s_sh/c_sh ready

    for (int k0 = 0; k0 < C; k0 += 8) {
        int k = k0 + lk;
        float4 rv = make_float4(0.f, 0.f, 0.f, 0.f);
        if (gi < N_NODES) rv = *(const float4*)(g_R + (size_t)gi * C + k);
        float4 wv = *(const float4*)(Wb + (size_t)lr * C + k);
        As[lk + 0][lr] = s_sh[k + 0] * rv.x + dg * c_sh[k + 0];
        As[lk + 1][lr] = s_sh[k + 1] * rv.y + dg * c_sh[k + 1];
        As[lk + 2][lr] = s_sh[k + 2] * rv.z + dg * c_sh[k + 2];
        As[lk + 3][lr] = s_sh[k + 3] * rv.w + dg * c_sh[k + 3];
        Ws[lk + 0][lr] = wv.x; Ws[lk + 1][lr] = wv.y; Ws[lk + 2][lr] = wv.z; Ws[lk + 3][lr] = wv.w;
        __syncthreads();
#pragma unroll
        for (int kk = 0; kk < 8; kk++) {
            float a[8], b[8];
#pragma unroll
            for (int m = 0; m < 8; m++) a[m] = As[kk][ty * 8 + m];
#pragma unroll
            for (int n = 0; n < 8; n++) b[n] = Ws[kk][tx * 8 + n];
#pragma unroll
            for (int m = 0; m < 8; m++)
#pragma unroll
                for (int n = 0; n < 8; n++) acc[m][n] = fmaf(a[m], b[n], acc[m][n]);
        }
        __syncthreads();
    }
    float* out = to_dout ? dout : g_B;
#pragma unroll
    for (int m = 0; m < 8; m++) {
        int go = i0 + ty * 8 + m;
        if (go < N_NODES) {
            float dgo = g_deg[go];
#pragma unroll
            for (int n = 0; n < 8; n += 4) {
                int j = tx * 8 + n;
                float4 v;
                v.x = acc[m][n + 0] + dgo * bbias[j + 0];
                v.y = acc[m][n + 1] + dgo * bbias[j + 1];
                v.z = acc[m][n + 2] + dgo * bbias[j + 2];
                v.w = acc[m][n + 3] + dgo * bbias[j + 3];
                *(float4*)(out + (size_t)go * C + j) = v;
            }
        }
    }
}

// ---------------- relu + row L2-normalize (g_B -> g_H) ---------------------
__global__ __launch_bounds__(256) void norm_kernel() {
    int row = (blockIdx.x * blockDim.x + threadIdx.x) >> 5;
    int lane = threadIdx.x & 31;
    if (row >= N_NODES) return;
    float4 v = *(const float4*)(g_B + (size_t)row * C + lane * 4);
    v.x = fmaxf(v.x, 0.f); v.y = fmaxf(v.y, 0.f);
    v.z = fmaxf(v.z, 0.f); v.w = fmaxf(v.w, 0.f);
    float ss = v.x * v.x + v.y * v.y + v.z * v.z + v.w * v.w;
#pragma unroll
    for (int o = 16; o; o >>= 1) ss += __shfl_xor_sync(0xFFFFFFFFu, ss, o);
    float inv = 1.f / fmaxf(sqrtf(ss), 1e-12f);
    v.x *= inv; v.y *= inv; v.z *= inv; v.w *= inv;
    *(float4*)(g_H + (size_t)row * C + lane * 4) = v;
}

// ---------------- launch ----------------------------------------------------
extern "C" void kernel_launch(void* const* d_in, const int* in_sizes, int n_in,
                              void* d_out, int out_size) {
    const float* x   = (const float*)d_in[0];
    const void*  ei  = d_in[1];
    const float* w1a = (const float*)d_in[2];
    const float* b1a = (const float*)d_in[3];
    const float* g1  = (const float*)d_in[4];
    const float* be1 = (const float*)d_in[5];
    const float* rm1 = (const float*)d_in[6];
    const float* rv1 = (const float*)d_in[7];
    const float* w1b = (const float*)d_in[8];
    const float* b1b = (const float*)d_in[9];
    const float* w2a = (const float*)d_in[10];
    const float* b2a = (const float*)d_in[11];
    const float* g2  = (const float*)d_in[12];
    const float* be2 = (const float*)d_in[13];
    const float* rm2 = (const float*)d_in[14];
    const float* rv2 = (const float*)d_in[15];
    const float* w2b = (const float*)d_in[16];
    const float* b2b = (const float*)d_in[17];
    float* out = (float*)d_out;

    const int ROWB = (N_NODES + 127) / 128;                 // 391
    const int ZB   = (N_NODES * C / 4 + 255) / 256;         // 6250
    const int EB   = (E_EDGES * 32) / 256;                  // 75000
    const int NB   = (N_NODES * 32 + 255) / 256;            // 6250

    detect_kernel<<<1, 32>>>(ei);
    convert_kernel<<<(2 * E_EDGES + 255) / 256, 256>>>(ei);
    prep_weights<<<(2 * 256 * C + 255) / 256, 256>>>(w1a, w2a);
    prep_sc<<<1, 256>>>(g1, be1, rm1, rv1, g2, be2, rm2, rv2);
    zero_kernel<<<ZB, 256>>>(1);
    deg_kernel<<<(E_EDGES + 255) / 256, 256>>>();

    // ---- layer 1 ----
    gemm_ab_kernel<<<dim3(ROWB, 2), 256>>>(x, b1a, 0, 0);
    edge_kernel<<<EB, 256>>>();
    gemm_out_kernel<<<ROWB, 256>>>(w1b, b1b, 0, out, 0);   // -> g_B scratch
    norm_kernel<<<NB, 256>>>();                            // g_B -> g_H

    // ---- layer 2 ----
    zero_kernel<<<ZB, 256>>>(0);
    gemm_ab_kernel<<<dim3(ROWB, 2), 256>>>(x, b2a, 1, 1);  // uses g_H
    edge_kernel<<<EB, 256>>>();
    gemm_out_kernel<<<ROWB, 256>>>(w2b, b2b, 1, out, 1);   // -> d_out
}

// round 3
// speedup vs baseline: 1.5940x; 1.5940x over previous
#include <cuda_runtime.h>
#include <cstdint>

#define NN 50000
#define C 128
#define EE 600000
#define PIT 20   // smem pitch (16 data + 4 pad) -> conflict-free mma fragment LDS

// ---------------- device scratch ----------------
__device__ float g_A[NN * C];
__device__ float g_B[NN * C];
__device__ float g_R[NN * C];
__device__ float g_H[NN * C];
__device__ float g_T[NN * C];
__device__ float g_deg[NN];
__device__ int   g_cnt[NN];
__device__ int   g_rowp[NN + 1];
__device__ int   g_offw[NN];
__device__ int   g_srcA[EE];
__device__ int   g_dstA[EE];
__device__ int   g_csr[EE];
__device__ int   g_is64;
__device__ float g_Wc[2][256 * C];   // rows 0..127 = WaL-WaR, 128..255 = WaR
__device__ float g_s[2][C];
__device__ float g_c[2][C];

// ---------------- helpers ----------------
__device__ __forceinline__ unsigned f2tf(float x) {
    unsigned r; asm("cvt.rna.tf32.f32 %0, %1;" : "=r"(r) : "f"(x)); return r;
}
__device__ __forceinline__ void mma8(float* c, unsigned a0, unsigned a1, unsigned a2, unsigned a3,
                                     unsigned b0, unsigned b1) {
    asm volatile("mma.sync.aligned.m16n8k8.row.col.f32.tf32.tf32.f32 "
                 "{%0,%1,%2,%3},{%4,%5,%6,%7},{%8,%9},{%0,%1,%2,%3};"
                 : "+f"(c[0]), "+f"(c[1]), "+f"(c[2]), "+f"(c[3])
                 : "r"(a0), "r"(a1), "r"(a2), "r"(a3), "r"(b0), "r"(b1));
}

// ---------------- prep / CSR build ----------------
__global__ void zero_cnt_kernel() {
    int i = blockIdx.x * blockDim.x + threadIdx.x;
    if (i < NN) g_cnt[i] = 0;
}

__global__ void detect_kernel(const void* __restrict__ ei) {
    int t = threadIdx.x;
    int bad = 0;
    if (t < 16) {
        long long v = ((const long long*)ei)[t];
        bad = (v < 0) || (v >= (long long)NN);
    }
    unsigned m = __ballot_sync(0xFFFFFFFFu, bad);
    if (t == 0) g_is64 = (m == 0);
}

__global__ void convert_hist_kernel(const void* __restrict__ ei) {
    int e = blockIdx.x * blockDim.x + threadIdx.x;
    if (e >= 2 * EE) return;
    int v;
    if (g_is64) v = (int)((const long long*)ei)[e];
    else        v = ((const int*)ei)[e];
    if (e < EE) g_srcA[e] = v;
    else {
        g_dstA[e - EE] = v;
        atomicAdd(&g_cnt[v], 1);
    }
}

__global__ void scan_kernel() {
    __shared__ int sm[1024];
    const int CH = 49;
    int t = threadIdx.x;
    int base = t * CH;
    int s = 0;
    for (int j = 0; j < CH; j++) {
        int i = base + j;
        if (i < NN) s += g_cnt[i];
    }
    sm[t] = s;
    __syncthreads();
    for (int off = 1; off < 1024; off <<= 1) {
        int v = (t >= off) ? sm[t - off] : 0;
        __syncthreads();
        sm[t] += v;
        __syncthreads();
    }
    int run = sm[t] - s;   // exclusive
    for (int j = 0; j < CH; j++) {
        int i = base + j;
        if (i < NN) {
            g_rowp[i] = run;
            g_offw[i] = run;
            run += g_cnt[i];
        }
    }
    if (t == 1023) g_rowp[NN] = run;
}

__global__ void scatter_kernel() {
    int e = blockIdx.x * blockDim.x + threadIdx.x;
    if (e >= EE) return;
    int d = g_dstA[e];
    int p = atomicAdd(&g_offw[d], 1);
    g_csr[p] = g_srcA[e];
}

__global__ void prep_weights(const float* __restrict__ w1a, const float* __restrict__ w2a) {
    int gid = blockIdx.x * blockDim.x + threadIdx.x;
    if (gid >= 2 * 256 * C) return;
    int layer = gid >> 15;
    int r = (gid >> 7) & 255;
    int k = gid & 127;
    const float* wa = layer ? w2a : w1a;
    float v;
    if (r < C) v = wa[r * (2 * C) + k] - wa[r * (2 * C) + C + k];
    else       v = wa[(r - C) * (2 * C) + C + k];
    g_Wc[layer][r * C + k] = v;
}

__global__ void prep_sc(const float* g1, const float* be1, const float* rm1, const float* rv1,
                        const float* g2, const float* be2, const float* rm2, const float* rv2) {
    int t = threadIdx.x;
    int layer = t >> 7;
    int k = t & 127;
    const float* g  = layer ? g2  : g1;
    const float* be = layer ? be2 : be1;
    const float* rm = layer ? rm2 : rm1;
    const float* rv = layer ? rv2 : rv1;
    float s = g[k] * rsqrtf(rv[k] + 1e-5f);
    g_s[layer][k] = s;
    g_c[layer][k] = be[k] - rm[k] * s;
}

// ---------------- 3xTF32 MMA GEMM -------------------------------------------
// mode 0 (AB): out[i,j] = X @ Wc[layer,half]^T (+ba on half 0); grid.y = half
// mode 1 (OUT): out[i,j] = (s*R[i,:] + deg[i]*c) @ Wg^T + deg[i]*bias[j]
__global__ __launch_bounds__(256) void mma_gemm(
    const float* __restrict__ Xg, const float* __restrict__ Wg,
    const float* __restrict__ bias, float* __restrict__ Og,
    int layer, int mode, int in_sel, int out_to_param)
{
    __shared__ unsigned AsH[128 * PIT], AsL[128 * PIT];
    __shared__ unsigned WsH[128 * PIT], WsL[128 * PIT];
    __shared__ float sv[C], cv[C];

    int tid = threadIdx.x;
    int i0 = blockIdx.x * 128;
    int half = blockIdx.y;

    const float* Xp = (mode == 1) ? g_R : (in_sel ? g_H : Xg);
    const float* Wp = (mode == 1) ? Wg : (&g_Wc[layer][half * C * C]);

    if (mode == 1 && tid < C) { sv[tid] = g_s[layer][tid]; cv[tid] = g_c[layer][tid]; }

    int lr = tid >> 1;              // loader row 0..127
    int koff = (tid & 1) * 8;       // loader k sub-offset
    int gi = i0 + lr;
    float dgl = 0.f;
    if (mode == 1 && gi < NN) dgl = g_deg[gi];
    const float* xr = Xp + (size_t)gi * C;
    const float* wr = Wp + (size_t)lr * C;

    int wid = tid >> 5, lane = tid & 31;
    int gid = lane >> 2, tig = lane & 3;
    int m0 = (wid & 1) * 64, n0 = (wid >> 1) * 32;

    float acc[4][4][4];
#pragma unroll
    for (int a = 0; a < 4; a++)
#pragma unroll
        for (int b = 0; b < 4; b++)
#pragma unroll
            for (int d = 0; d < 4; d++) acc[a][b][d] = 0.f;

    __syncthreads();   // sv/cv ready

    for (int kc = 0; kc < 8; kc++) {
        int gk = kc * 16 + koff;
        // --- load X chunk (with optional affine transform), split tf32 hi/lo ---
        float xv[8];
        if (gi < NN) {
            float4 v0 = *(const float4*)(xr + gk);
            float4 v1 = *(const float4*)(xr + gk + 4);
            xv[0] = v0.x; xv[1] = v0.y; xv[2] = v0.z; xv[3] = v0.w;
            xv[4] = v1.x; xv[5] = v1.y; xv[6] = v1.z; xv[7] = v1.w;
        } else {
#pragma unroll
            for (int j = 0; j < 8; j++) xv[j] = 0.f;
        }
        if (mode == 1) {
#pragma unroll
            for (int j = 0; j < 8; j++) xv[j] = sv[gk + j] * xv[j] + dgl * cv[gk + j];
        }
#pragma unroll
        for (int j = 0; j < 8; j++) {
            unsigned h = f2tf(xv[j]);
            AsH[lr * PIT + koff + j] = h;
            AsL[lr * PIT + koff + j] = f2tf(xv[j] - __uint_as_float(h));
        }
        // --- load W chunk ---
        {
            float4 w0 = *(const float4*)(wr + gk);
            float4 w1 = *(const float4*)(wr + gk + 4);
            float wvv[8] = {w0.x, w0.y, w0.z, w0.w, w1.x, w1.y, w1.z, w1.w};
#pragma unroll
            for (int j = 0; j < 8; j++) {
                unsigned h = f2tf(wvv[j]);
                WsH[lr * PIT + koff + j] = h;
                WsL[lr * PIT + koff + j] = f2tf(wvv[j] - __uint_as_float(h));
            }
        }
        __syncthreads();

#pragma unroll
        for (int ks = 0; ks < 2; ks++) {
            int kb = ks * 8;
            unsigned bh0[4], bh1[4], bl0[4], bl1[4];
#pragma unroll
            for (int nt = 0; nt < 4; nt++) {
                int n = n0 + nt * 8 + gid;
                bh0[nt] = WsH[n * PIT + kb + tig];
                bh1[nt] = WsH[n * PIT + kb + tig + 4];
                bl0[nt] = WsL[n * PIT + kb + tig];
                bl1[nt] = WsL[n * PIT + kb + tig + 4];
            }
#pragma unroll
            for (int mt = 0; mt < 4; mt++) {
                int m = m0 + mt * 16 + gid;
                unsigned ah0 = AsH[m * PIT + kb + tig];
                unsigned ah1 = AsH[(m + 8) * PIT + kb + tig];
                unsigned ah2 = AsH[m * PIT + kb + tig + 4];
                unsigned ah3 = AsH[(m + 8) * PIT + kb + tig + 4];
                unsigned al0 = AsL[m * PIT + kb + tig];
                unsigned al1 = AsL[(m + 8) * PIT + kb + tig];
                unsigned al2 = AsL[m * PIT + kb + tig + 4];
                unsigned al3 = AsL[(m + 8) * PIT + kb + tig + 4];
#pragma unroll
                for (int nt = 0; nt < 4; nt++) {
                    mma8(acc[mt][nt], ah0, ah1, ah2, ah3, bh0[nt], bh1[nt]);
                    mma8(acc[mt][nt], ah0, ah1, ah2, ah3, bl0[nt], bl1[nt]);
                    mma8(acc[mt][nt], al0, al1, al2, al3, bh0[nt], bh1[nt]);
                }
            }
        }
        __syncthreads();
    }

    // --- epilogue ---
    float* outp;
    if (mode == 1) outp = out_to_param ? Og : g_T;
    else           outp = half ? g_B : g_A;
#pragma unroll
    for (int mt = 0; mt < 4; mt++) {
        int r0 = i0 + m0 + mt * 16 + gid;
        int r1 = r0 + 8;
#pragma unroll
        for (int nt = 0; nt < 4; nt++) {
            int col = n0 + nt * 8 + 2 * tig;
            float* cc = acc[mt][nt];
            if (mode == 0) {
                float b0 = 0.f, b1 = 0.f;
                if (half == 0) { b0 = bias[col]; b1 = bias[col + 1]; }
                if (r0 < NN) { float2 v = {cc[0] + b0, cc[1] + b1}; *(float2*)(outp + (size_t)r0 * C + col) = v; }
                if (r1 < NN) { float2 v = {cc[2] + b0, cc[3] + b1}; *(float2*)(outp + (size_t)r1 * C + col) = v; }
            } else {
                float bb0 = bias[col], bb1 = bias[col + 1];
                if (r0 < NN) { float d = g_deg[r0]; float2 v = {cc[0] + d * bb0, cc[1] + d * bb1}; *(float2*)(outp + (size_t)r0 * C + col) = v; }
                if (r1 < NN) { float d = g_deg[r1]; float2 v = {cc[2] + d * bb0, cc[3] + d * bb1}; *(float2*)(outp + (size_t)r1 * C + col) = v; }
            }
        }
    }
}

// ---------------- CSR edge aggregate: R[i] = sum relu(A[i] + B[src]) -------
__global__ __launch_bounds__(256) void edge_csr_kernel() {
    int node = (blockIdx.x * blockDim.x + threadIdx.x) >> 5;
    int lane = threadIdx.x & 31;
    if (node >= NN) return;
    int s0 = g_rowp[node], s1 = g_rowp[node + 1];
    float4 a = ((const float4*)(g_A + (size_t)node * C))[lane];
    float4 acc = make_float4(0.f, 0.f, 0.f, 0.f);
    int e = s0;
    for (; e + 1 < s1; e += 2) {
        int sa = g_csr[e], sb = g_csr[e + 1];
        float4 b0 = ((const float4*)(g_B + (size_t)sa * C))[lane];
        float4 b1 = ((const float4*)(g_B + (size_t)sb * C))[lane];
        acc.x += fmaxf(a.x + b0.x, 0.f) + fmaxf(a.x + b1.x, 0.f);
        acc.y += fmaxf(a.y + b0.y, 0.f) + fmaxf(a.y + b1.y, 0.f);
        acc.z += fmaxf(a.z + b0.z, 0.f) + fmaxf(a.z + b1.z, 0.f);
        acc.w += fmaxf(a.w + b0.w, 0.f) + fmaxf(a.w + b1.w, 0.f);
    }
    if (e < s1) {
        int sa = g_csr[e];
        float4 b0 = ((const float4*)(g_B + (size_t)sa * C))[lane];
        acc.x += fmaxf(a.x + b0.x, 0.f);
        acc.y += fmaxf(a.y + b0.y, 0.f);
        acc.z += fmaxf(a.z + b0.z, 0.f);
        acc.w += fmaxf(a.w + b0.w, 0.f);
    }
    ((float4*)(g_R + (size_t)node * C))[lane] = acc;
    if (lane == 0) g_deg[node] = (float)(s1 - s0);
}

// ---------------- relu + row L2-normalize (g_T -> g_H) ---------------------
__global__ __launch_bounds__(256) void norm_kernel() {
    int row = (blockIdx.x * blockDim.x + threadIdx.x) >> 5;
    int lane = threadIdx.x & 31;
    if (row >= NN) return;
    float4 v = ((const float4*)(g_T + (size_t)row * C))[lane];
    v.x = fmaxf(v.x, 0.f); v.y = fmaxf(v.y, 0.f);
    v.z = fmaxf(v.z, 0.f); v.w = fmaxf(v.w, 0.f);
    float ss = v.x * v.x + v.y * v.y + v.z * v.z + v.w * v.w;
#pragma unroll
    for (int o = 16; o; o >>= 1) ss += __shfl_xor_sync(0xFFFFFFFFu, ss, o);
    float inv = 1.f / fmaxf(sqrtf(ss), 1e-12f);
    v.x *= inv; v.y *= inv; v.z *= inv; v.w *= inv;
    ((float4*)(g_H + (size_t)row * C))[lane] = v;
}

// ---------------- launch ----------------------------------------------------
extern "C" void kernel_launch(void* const* d_in, const int* in_sizes, int n_in,
                              void* d_out, int out_size) {
    const float* x   = (const float*)d_in[0];
    const void*  ei  = d_in[1];
    const float* w1a = (const float*)d_in[2];
    const float* b1a = (const float*)d_in[3];
    const float* g1  = (const float*)d_in[4];
    const float* be1 = (const float*)d_in[5];
    const float* rm1 = (const float*)d_in[6];
    const float* rv1 = (const float*)d_in[7];
    const float* w1b = (const float*)d_in[8];
    const float* b1b = (const float*)d_in[9];
    const float* w2a = (const float*)d_in[10];
    const float* b2a = (const float*)d_in[11];
    const float* g2  = (const float*)d_in[12];
    const float* be2 = (const float*)d_in[13];
    const float* rm2 = (const float*)d_in[14];
    const float* rv2 = (const float*)d_in[15];
    const float* w2b = (const float*)d_in[16];
    const float* b2b = (const float*)d_in[17];
    float* out = (float*)d_out;

    const int ROWB = (NN + 127) / 128;          // 391
    const int EB   = (NN * 32 + 255) / 256;     // warp-per-node blocks: 6250

    zero_cnt_kernel<<<(NN + 255) / 256, 256>>>();
    detect_kernel<<<1, 32>>>(ei);
    convert_hist_kernel<<<(2 * EE + 255) / 256, 256>>>(ei);
    scan_kernel<<<1, 1024>>>();
    scatter_kernel<<<(EE + 255) / 256, 256>>>();
    prep_weights<<<(2 * 256 * C + 255) / 256, 256>>>(w1a, w2a);
    prep_sc<<<1, 256>>>(g1, be1, rm1, rv1, g2, be2, rm2, rv2);

    // ---- layer 1 ----
    mma_gemm<<<dim3(ROWB, 2), 256>>>(x, nullptr, b1a, nullptr, 0, 0, 0, 0);   // -> g_A, g_B
    edge_csr_kernel<<<EB, 256>>>();                                           // -> g_R, g_deg
    mma_gemm<<<dim3(ROWB, 1), 256>>>(nullptr, w1b, b1b, nullptr, 0, 1, 0, 0); // -> g_T
    norm_kernel<<<EB, 256>>>();                                               // g_T -> g_H

    // ---- layer 2 ----
    mma_gemm<<<dim3(ROWB, 2), 256>>>(nullptr, nullptr, b2a, nullptr, 1, 0, 1, 0); // g_H -> g_A, g_B
    edge_csr_kernel<<<EB, 256>>>();
    mma_gemm<<<dim3(ROWB, 1), 256>>>(nullptr, w2b, b2b, out, 1, 1, 0, 1);     // -> d_out
}

// round 4
// speedup vs baseline: 1.9085x; 1.1973x over previous
#include <cuda_runtime.h>
#include <cstdint>

#define NN 50000
#define C 128
#define EE 600000
#define PIT 20   // smem pitch (16 data + 4 pad) -> conflict-free mma fragment LDS
#define SCAN_NB 196   // (NN + 255) / 256

// ---------------- device scratch ----------------
__device__ float g_A[NN * C];
__device__ float g_B[NN * C];
__device__ float g_R[NN * C];
__device__ float g_H[NN * C];
__device__ float g_T[NN * C];
__device__ float g_deg[NN];
__device__ int   g_cnt[NN];
__device__ int   g_rowp[NN + 1];
__device__ int   g_offw[NN];
__device__ int   g_bsum[256];
__device__ int   g_boff[256];
__device__ int   g_srcA[EE];
__device__ int   g_dstA[EE];
__device__ int   g_csr[EE];
__device__ int   g_is64;
__device__ float g_Wc[2][256 * C];   // rows 0..127 = WaL-WaR, 128..255 = WaR
__device__ float g_s[2][C];
__device__ float g_c[2][C];

// ---------------- helpers ----------------
__device__ __forceinline__ unsigned f2tf(float x) {
    unsigned r; asm("cvt.rna.tf32.f32 %0, %1;" : "=r"(r) : "f"(x)); return r;
}
__device__ __forceinline__ void mma8(float* c, unsigned a0, unsigned a1, unsigned a2, unsigned a3,
                                     unsigned b0, unsigned b1) {
    asm volatile("mma.sync.aligned.m16n8k8.row.col.f32.tf32.tf32.f32 "
                 "{%0,%1,%2,%3},{%4,%5,%6,%7},{%8,%9},{%0,%1,%2,%3};"
                 : "+f"(c[0]), "+f"(c[1]), "+f"(c[2]), "+f"(c[3])
                 : "r"(a0), "r"(a1), "r"(a2), "r"(a3), "r"(b0), "r"(b1));
}

// ---------------- prep / CSR build ----------------
__global__ void zero_cnt_kernel() {
    int i = blockIdx.x * blockDim.x + threadIdx.x;
    if (i < NN) g_cnt[i] = 0;
}

__global__ void detect_kernel(const void* __restrict__ ei) {
    int t = threadIdx.x;
    int bad = 0;
    if (t < 16) {
        long long v = ((const long long*)ei)[t];
        bad = (v < 0) || (v >= (long long)NN);
    }
    unsigned m = __ballot_sync(0xFFFFFFFFu, bad);
    if (t == 0) g_is64 = (m == 0);
}

__global__ void convert_hist_kernel(const void* __restrict__ ei) {
    int e = blockIdx.x * blockDim.x + threadIdx.x;
    if (e >= 2 * EE) return;
    int v;
    if (g_is64) v = (int)((const long long*)ei)[e];
    else        v = ((const int*)ei)[e];
    if (e < EE) g_srcA[e] = v;
    else {
        g_dstA[e - EE] = v;
        atomicAdd(&g_cnt[v], 1);
    }
}

// ---- multi-block exclusive scan of g_cnt -> g_rowp / g_offw ----
__global__ void scan_local() {
    __shared__ int sm[256];
    int t = threadIdx.x;
    int i = blockIdx.x * 256 + t;
    int v = (i < NN) ? g_cnt[i] : 0;
    sm[t] = v;
    __syncthreads();
#pragma unroll
    for (int off = 1; off < 256; off <<= 1) {
        int u = (t >= off) ? sm[t - off] : 0;
        __syncthreads();
        sm[t] += u;
        __syncthreads();
    }
    if (i < NN) g_rowp[i] = sm[t] - v;          // local exclusive prefix
    if (t == 255) g_bsum[blockIdx.x] = sm[255]; // block total
}

__global__ void scan_bsum() {
    __shared__ int sm[256];
    int t = threadIdx.x;
    int v = (t < SCAN_NB) ? g_bsum[t] : 0;
    sm[t] = v;
    __syncthreads();
#pragma unroll
    for (int off = 1; off < 256; off <<= 1) {
        int u = (t >= off) ? sm[t - off] : 0;
        __syncthreads();
        sm[t] += u;
        __syncthreads();
    }
    g_boff[t] = sm[t] - v;                       // exclusive
    if (t == 255) g_rowp[NN] = sm[255];          // total = EE
}

__global__ void scan_add() {
    int i = blockIdx.x * 256 + threadIdx.x;
    if (i >= NN) return;
    int r = g_rowp[i] + g_boff[blockIdx.x];
    g_rowp[i] = r;
    g_offw[i] = r;
}

__global__ void scatter_kernel() {
    int e = blockIdx.x * blockDim.x + threadIdx.x;
    if (e >= EE) return;
    int d = g_dstA[e];
    int p = atomicAdd(&g_offw[d], 1);
    g_csr[p] = g_srcA[e];
}

__global__ void prep_weights(const float* __restrict__ w1a, const float* __restrict__ w2a) {
    int gid = blockIdx.x * blockDim.x + threadIdx.x;
    if (gid >= 2 * 256 * C) return;
    int layer = gid >> 15;
    int r = (gid >> 7) & 255;
    int k = gid & 127;
    const float* wa = layer ? w2a : w1a;
    float v;
    if (r < C) v = wa[r * (2 * C) + k] - wa[r * (2 * C) + C + k];
    else       v = wa[(r - C) * (2 * C) + C + k];
    g_Wc[layer][r * C + k] = v;
}

__global__ void prep_sc(const float* g1, const float* be1, const float* rm1, const float* rv1,
                        const float* g2, const float* be2, const float* rm2, const float* rv2) {
    int t = threadIdx.x;
    int layer = t >> 7;
    int k = t & 127;
    const float* g  = layer ? g2  : g1;
    const float* be = layer ? be2 : be1;
    const float* rm = layer ? rm2 : rm1;
    const float* rv = layer ? rv2 : rv1;
    float s = g[k] * rsqrtf(rv[k] + 1e-5f);
    g_s[layer][k] = s;
    g_c[layer][k] = be[k] - rm[k] * s;
}

// ---------------- 3xTF32 MMA GEMM -------------------------------------------
// mode 0 (AB): out[i,j] = X @ Wc[layer,half]^T (+ba on half 0); grid.y = half
// mode 1 (OUT): out[i,j] = (s*R[i,:] + deg[i]*c) @ Wg^T + deg[i]*bias[j]
__global__ __launch_bounds__(256) void mma_gemm(
    const float* __restrict__ Xg, const float* __restrict__ Wg,
    const float* __restrict__ bias, float* __restrict__ Og,
    int layer, int mode, int in_sel, int out_to_param)
{
    __shared__ unsigned AsH[128 * PIT], AsL[128 * PIT];
    __shared__ unsigned WsH[128 * PIT], WsL[128 * PIT];
    __shared__ float sv[C], cv[C];

    int tid = threadIdx.x;
    int i0 = blockIdx.x * 128;
    int half = blockIdx.y;

    const float* Xp = (mode == 1) ? g_R : (in_sel ? g_H : Xg);
    const float* Wp = (mode == 1) ? Wg : (&g_Wc[layer][half * C * C]);

    if (mode == 1 && tid < C) { sv[tid] = g_s[layer][tid]; cv[tid] = g_c[layer][tid]; }

    int lr = tid >> 1;              // loader row 0..127
    int koff = (tid & 1) * 8;       // loader k sub-offset
    int gi = i0 + lr;
    float dgl = 0.f;
    if (mode == 1 && gi < NN) dgl = g_deg[gi];
    const float* xr = Xp + (size_t)gi * C;
    const float* wr = Wp + (size_t)lr * C;

    int wid = tid >> 5, lane = tid & 31;
    int gid = lane >> 2, tig = lane & 3;
    int m0 = (wid & 1) * 64, n0 = (wid >> 1) * 32;

    float acc[4][4][4];
#pragma unroll
    for (int a = 0; a < 4; a++)
#pragma unroll
        for (int b = 0; b < 4; b++)
#pragma unroll
            for (int d = 0; d < 4; d++) acc[a][b][d] = 0.f;

    __syncthreads();   // sv/cv ready

    for (int kc = 0; kc < 8; kc++) {
        int gk = kc * 16 + koff;
        // --- load X chunk (with optional affine transform), split tf32 hi/lo ---
        float xv[8];
        if (gi < NN) {
            float4 v0 = *(const float4*)(xr + gk);
            float4 v1 = *(const float4*)(xr + gk + 4);
            xv[0] = v0.x; xv[1] = v0.y; xv[2] = v0.z; xv[3] = v0.w;
            xv[4] = v1.x; xv[5] = v1.y; xv[6] = v1.z; xv[7] = v1.w;
        } else {
#pragma unroll
            for (int j = 0; j < 8; j++) xv[j] = 0.f;
        }
        if (mode == 1) {
#pragma unroll
            for (int j = 0; j < 8; j++) xv[j] = sv[gk + j] * xv[j] + dgl * cv[gk + j];
        }
#pragma unroll
        for (int j = 0; j < 8; j++) {
            unsigned h = f2tf(xv[j]);
            AsH[lr * PIT + koff + j] = h;
            AsL[lr * PIT + koff + j] = f2tf(xv[j] - __uint_as_float(h));
        }
        // --- load W chunk ---
        {
            float4 w0 = *(const float4*)(wr + gk);
            float4 w1 = *(const float4*)(wr + gk + 4);
            float wvv[8] = {w0.x, w0.y, w0.z, w0.w, w1.x, w1.y, w1.z, w1.w};
#pragma unroll
            for (int j = 0; j < 8; j++) {
                unsigned h = f2tf(wvv[j]);
                WsH[lr * PIT + koff + j] = h;
                WsL[lr * PIT + koff + j] = f2tf(wvv[j] - __uint_as_float(h));
            }
        }
        __syncthreads();

#pragma unroll
        for (int ks = 0; ks < 2; ks++) {
            int kb = ks * 8;
            unsigned bh0[4], bh1[4], bl0[4], bl1[4];
#pragma unroll
            for (int nt = 0; nt < 4; nt++) {
                int n = n0 + nt * 8 + gid;
                bh0[nt] = WsH[n * PIT + kb + tig];
                bh1[nt] = WsH[n * PIT + kb + tig + 4];
                bl0[nt] = WsL[n * PIT + kb + tig];
                bl1[nt] = WsL[n * PIT + kb + tig + 4];
            }
#pragma unroll
            for (int mt = 0; mt < 4; mt++) {
                int m = m0 + mt * 16 + gid;
                unsigned ah0 = AsH[m * PIT + kb + tig];
                unsigned ah1 = AsH[(m + 8) * PIT + kb + tig];
                unsigned ah2 = AsH[m * PIT + kb + tig + 4];
                unsigned ah3 = AsH[(m + 8) * PIT + kb + tig + 4];
                unsigned al0 = AsL[m * PIT + kb + tig];
                unsigned al1 = AsL[(m + 8) * PIT + kb + tig];
                unsigned al2 = AsL[m * PIT + kb + tig + 4];
                unsigned al3 = AsL[(m + 8) * PIT + kb + tig + 4];
#pragma unroll
                for (int nt = 0; nt < 4; nt++) {
                    mma8(acc[mt][nt], ah0, ah1, ah2, ah3, bh0[nt], bh1[nt]);
                    mma8(acc[mt][nt], ah0, ah1, ah2, ah3, bl0[nt], bl1[nt]);
                    mma8(acc[mt][nt], al0, al1, al2, al3, bh0[nt], bh1[nt]);
                }
            }
        }
        __syncthreads();
    }

    // --- epilogue ---
    float* outp;
    if (mode == 1) outp = out_to_param ? Og : g_T;
    else           outp = half ? g_B : g_A;
#pragma unroll
    for (int mt = 0; mt < 4; mt++) {
        int r0 = i0 + m0 + mt * 16 + gid;
        int r1 = r0 + 8;
#pragma unroll
        for (int nt = 0; nt < 4; nt++) {
            int col = n0 + nt * 8 + 2 * tig;
            float* cc = acc[mt][nt];
            if (mode == 0) {
                float b0 = 0.f, b1 = 0.f;
                if (half == 0) { b0 = bias[col]; b1 = bias[col + 1]; }
                if (r0 < NN) { float2 v = {cc[0] + b0, cc[1] + b1}; *(float2*)(outp + (size_t)r0 * C + col) = v; }
                if (r1 < NN) { float2 v = {cc[2] + b0, cc[3] + b1}; *(float2*)(outp + (size_t)r1 * C + col) = v; }
            } else {
                float bb0 = bias[col], bb1 = bias[col + 1];
                if (r0 < NN) { float d = g_deg[r0]; float2 v = {cc[0] + d * bb0, cc[1] + d * bb1}; *(float2*)(outp + (size_t)r0 * C + col) = v; }
                if (r1 < NN) { float d = g_deg[r1]; float2 v = {cc[2] + d * bb0, cc[3] + d * bb1}; *(float2*)(outp + (size_t)r1 * C + col) = v; }
            }
        }
    }
}

// ---------------- CSR edge aggregate: R[i] = sum relu(A[i] + B[src]) -------
__global__ __launch_bounds__(256) void edge_csr_kernel() {
    int node = (blockIdx.x * blockDim.x + threadIdx.x) >> 5;
    int lane = threadIdx.x & 31;
    if (node >= NN) return;
    int s0 = g_rowp[node], s1 = g_rowp[node + 1];
    float4 a = ((const float4*)(g_A + (size_t)node * C))[lane];
    float4 acc = make_float4(0.f, 0.f, 0.f, 0.f);
    int e = s0;
    for (; e + 1 < s1; e += 2) {
        int sa = g_csr[e], sb = g_csr[e + 1];
        float4 b0 = ((const float4*)(g_B + (size_t)sa * C))[lane];
        float4 b1 = ((const float4*)(g_B + (size_t)sb * C))[lane];
        acc.x += fmaxf(a.x + b0.x, 0.f) + fmaxf(a.x + b1.x, 0.f);
        acc.y += fmaxf(a.y + b0.y, 0.f) + fmaxf(a.y + b1.y, 0.f);
        acc.z += fmaxf(a.z + b0.z, 0.f) + fmaxf(a.z + b1.z, 0.f);
        acc.w += fmaxf(a.w + b0.w, 0.f) + fmaxf(a.w + b1.w, 0.f);
    }
    if (e < s1) {
        int sa = g_csr[e];
        float4 b0 = ((const float4*)(g_B + (size_t)sa * C))[lane];
        acc.x += fmaxf(a.x + b0.x, 0.f);
        acc.y += fmaxf(a.y + b0.y, 0.f);
        acc.z += fmaxf(a.z + b0.z, 0.f);
        acc.w += fmaxf(a.w + b0.w, 0.f);
    }
    ((float4*)(g_R + (size_t)node * C))[lane] = acc;
    if (lane == 0) g_deg[node] = (float)(s1 - s0);
}

// ---------------- relu + row L2-normalize (g_T -> g_H) ---------------------
__global__ __launch_bounds__(256) void norm_kernel() {
    int row = (blockIdx.x * blockDim.x + threadIdx.x) >> 5;
    int lane = threadIdx.x & 31;
    if (row >= NN) return;
    float4 v = ((const float4*)(g_T + (size_t)row * C))[lane];
    v.x = fmaxf(v.x, 0.f); v.y = fmaxf(v.y, 0.f);
    v.z = fmaxf(v.z, 0.f); v.w = fmaxf(v.w, 0.f);
    float ss = v.x * v.x + v.y * v.y + v.z * v.z + v.w * v.w;
#pragma unroll
    for (int o = 16; o; o >>= 1) ss += __shfl_xor_sync(0xFFFFFFFFu, ss, o);
    float inv = 1.f / fmaxf(sqrtf(ss), 1e-12f);
    v.x *= inv; v.y *= inv; v.z *= inv; v.w *= inv;
    ((float4*)(g_H + (size_t)row * C))[lane] = v;
}

// ---------------- launch ----------------------------------------------------
extern "C" void kernel_launch(void* const* d_in, const int* in_sizes, int n_in,
                              void* d_out, int out_size) {
    const float* x   = (const float*)d_in[0];
    const void*  ei  = d_in[1];
    const float* w1a = (const float*)d_in[2];
    const float* b1a = (const float*)d_in[3];
    const float* g1  = (const float*)d_in[4];
    const float* be1 = (const float*)d_in[5];
    const float* rm1 = (const float*)d_in[6];
    const float* rv1 = (const float*)d_in[7];
    const float* w1b = (const float*)d_in[8];
    const float* b1b = (const float*)d_in[9];
    const float* w2a = (const float*)d_in[10];
    const float* b2a = (const float*)d_in[11];
    const float* g2  = (const float*)d_in[12];
    const float* be2 = (const float*)d_in[13];
    const float* rm2 = (const float*)d_in[14];
    const float* rv2 = (const float*)d_in[15];
    const float* w2b = (const float*)d_in[16];
    const float* b2b = (const float*)d_in[17];
    float* out = (float*)d_out;

    const int ROWB = (NN + 127) / 128;          // 391
    const int EB   = (NN * 32 + 255) / 256;     // warp-per-node blocks: 6250

    zero_cnt_kernel<<<SCAN_NB, 256>>>();
    detect_kernel<<<1, 32>>>(ei);
    convert_hist_kernel<<<(2 * EE + 255) / 256, 256>>>(ei);
    scan_local<<<SCAN_NB, 256>>>();
    scan_bsum<<<1, 256>>>();
    scan_add<<<SCAN_NB, 256>>>();
    scatter_kernel<<<(EE + 255) / 256, 256>>>();
    prep_weights<<<(2 * 256 * C + 255) / 256, 256>>>(w1a, w2a);
    prep_sc<<<1, 256>>>(g1, be1, rm1, rv1, g2, be2, rm2, rv2);

    // ---- layer 1 ----
    mma_gemm<<<dim3(ROWB, 2), 256>>>(x, nullptr, b1a, nullptr, 0, 0, 0, 0);   // -> g_A, g_B
    edge_csr_kernel<<<EB, 256>>>();                                           // -> g_R, g_deg
    mma_gemm<<<dim3(ROWB, 1), 256>>>(nullptr, w1b, b1b, nullptr, 0, 1, 0, 0); // -> g_T
    norm_kernel<<<EB, 256>>>();                                               // g_T -> g_H

    // ---- layer 2 ----
    mma_gemm<<<dim3(ROWB, 2), 256>>>(nullptr, nullptr, b2a, nullptr, 1, 0, 1, 0); // g_H -> g_A, g_B
    edge_csr_kernel<<<EB, 256>>>();
    mma_gemm<<<dim3(ROWB, 1), 256>>>(nullptr, w2b, b2b, out, 1, 1, 0, 1);     // -> d_out
}

// round 5
// speedup vs baseline: 2.6082x; 1.3666x over previous
#include <cuda_runtime.h>
#include <cstdint>

#define NN 50000
#define C 128
#define EE 600000
#define PIT 13        // smem pitch in u32 pairs (8 data + 5 pad) -> conflict-free
#define SCAN_NB 196   // (NN + 255) / 256

// ---------------- device scratch ----------------
__device__ float g_A[NN * C];
__device__ float g_B[NN * C];
__device__ float g_R[NN * C];
__device__ float g_H[NN * C];
__device__ float g_deg[NN];
__device__ int   g_cnt[NN];
__device__ int   g_rowp[NN + 1];
__device__ int   g_offw[NN];
__device__ int   g_bsum[256];
__device__ int   g_boff[256];
__device__ int   g_srcA[EE];
__device__ int   g_dstA[EE];
__device__ int   g_csr[EE];
__device__ int   g_is64;
__device__ float g_Wc[2][256 * C];   // rows 0..127 = WaL-WaR, 128..255 = WaR
__device__ float g_s[2][C];
__device__ float g_c[2][C];

// ---------------- helpers ----------------
__device__ __forceinline__ unsigned pack_bf(float hi, float lo) {
    unsigned r; asm("cvt.rn.bf16x2.f32 %0, %1, %2;" : "=r"(r) : "f"(hi), "f"(lo)); return r;
}
__device__ __forceinline__ void mma16(float* c, unsigned a0, unsigned a1, unsigned a2, unsigned a3,
                                      unsigned b0, unsigned b1) {
    asm volatile("mma.sync.aligned.m16n8k16.row.col.f32.bf16.bf16.f32 "
                 "{%0,%1,%2,%3},{%4,%5,%6,%7},{%8,%9},{%0,%1,%2,%3};"
                 : "+f"(c[0]), "+f"(c[1]), "+f"(c[2]), "+f"(c[3])
                 : "r"(a0), "r"(a1), "r"(a2), "r"(a3), "r"(b0), "r"(b1));
}
// split 2 floats -> bf16 hi-pair and residual lo-pair
__device__ __forceinline__ void split2(float x0, float x1, unsigned& h, unsigned& l) {
    h = pack_bf(x1, x0);
    float lo0 = __uint_as_float(h << 16);
    float hi1 = __uint_as_float(h & 0xFFFF0000u);
    l = pack_bf(x1 - hi1, x0 - lo0);
}

// ---------------- fused prep: zero cnt + combined weights + BN affine ------
__global__ void prep_all(const float* __restrict__ w1a, const float* __restrict__ w2a,
                         const float* g1, const float* be1, const float* rm1, const float* rv1,
                         const float* g2, const float* be2, const float* rm2, const float* rv2) {
    int gid = blockIdx.x * blockDim.x + threadIdx.x;   // 65536 threads
    if (gid < NN) g_cnt[gid] = 0;
    if (gid < 2 * 256 * C) {
        int layer = gid >> 15;
        int r = (gid >> 7) & 255;
        int k = gid & 127;
        const float* wa = layer ? w2a : w1a;
        float v;
        if (r < C) v = wa[r * (2 * C) + k] - wa[r * (2 * C) + C + k];
        else       v = wa[(r - C) * (2 * C) + C + k];
        g_Wc[layer][r * C + k] = v;
    }
    if (gid < 256) {
        int layer = gid >> 7;
        int k = gid & 127;
        const float* g  = layer ? g2  : g1;
        const float* be = layer ? be2 : be1;
        const float* rm = layer ? rm2 : rm1;
        const float* rv = layer ? rv2 : rv1;
        float s = g[k] * rsqrtf(rv[k] + 1e-5f);
        g_s[layer][k] = s;
        g_c[layer][k] = be[k] - rm[k] * s;
    }
}

__global__ void detect_kernel(const void* __restrict__ ei) {
    int t = threadIdx.x;
    int bad = 0;
    if (t < 16) {
        long long v = ((const long long*)ei)[t];
        bad = (v < 0) || (v >= (long long)NN);
    }
    unsigned m = __ballot_sync(0xFFFFFFFFu, bad);
    if (t == 0) g_is64 = (m == 0);
}

__global__ void convert_hist_kernel(const void* __restrict__ ei) {
    int e = blockIdx.x * blockDim.x + threadIdx.x;
    if (e >= 2 * EE) return;
    int v;
    if (g_is64) v = (int)((const long long*)ei)[e];
    else        v = ((const int*)ei)[e];
    if (e < EE) g_srcA[e] = v;
    else {
        g_dstA[e - EE] = v;
        atomicAdd(&g_cnt[v], 1);
    }
}

// ---- multi-block exclusive scan of g_cnt -> g_rowp / g_offw ----
__global__ void scan_local() {
    __shared__ int sm[256];
    int t = threadIdx.x;
    int i = blockIdx.x * 256 + t;
    int v = (i < NN) ? g_cnt[i] : 0;
    sm[t] = v;
    __syncthreads();
#pragma unroll
    for (int off = 1; off < 256; off <<= 1) {
        int u = (t >= off) ? sm[t - off] : 0;
        __syncthreads();
        sm[t] += u;
        __syncthreads();
    }
    if (i < NN) g_rowp[i] = sm[t] - v;
    if (t == 255) g_bsum[blockIdx.x] = sm[255];
}

__global__ void scan_bsum() {
    __shared__ int sm[256];
    int t = threadIdx.x;
    int v = (t < SCAN_NB) ? g_bsum[t] : 0;
    sm[t] = v;
    __syncthreads();
#pragma unroll
    for (int off = 1; off < 256; off <<= 1) {
        int u = (t >= off) ? sm[t - off] : 0;
        __syncthreads();
        sm[t] += u;
        __syncthreads();
    }
    g_boff[t] = sm[t] - v;
    if (t == 255) g_rowp[NN] = sm[255];
}

__global__ void scan_add() {
    int i = blockIdx.x * 256 + threadIdx.x;
    if (i >= NN) return;
    int r = g_rowp[i] + g_boff[blockIdx.x];
    g_rowp[i] = r;
    g_offw[i] = r;
}

__global__ void scatter_kernel() {
    int e = blockIdx.x * blockDim.x + threadIdx.x;
    if (e >= EE) return;
    int d = g_dstA[e];
    int p = atomicAdd(&g_offw[d], 1);
    g_csr[p] = g_srcA[e];
}

// ---------------- 3xBF16 MMA GEMM -------------------------------------------
// mode 0 (AB): out = X @ Wc[layer,half]^T (+ba on half 0); grid.y = half
// mode 1 (OUT): out = (s*R + deg*c) @ Wg^T + deg*bias ; optional fused relu+L2norm
__global__ __launch_bounds__(256) void mma_gemm(
    const float* __restrict__ Xg, const float* __restrict__ Wg,
    const float* __restrict__ bias, float* __restrict__ Og,
    int layer, int mode, int in_sel, int do_norm)
{
    __shared__ unsigned AsH[128 * PIT], AsL[128 * PIT];
    __shared__ unsigned WsH[128 * PIT], WsL[128 * PIT];
    __shared__ float sv[C], cv[C];
    __shared__ float rowss[128];

    int tid = threadIdx.x;
    int i0 = blockIdx.x * 128;
    int half = blockIdx.y;

    const float* Xp = (mode == 1) ? g_R : (in_sel ? g_H : Xg);
    const float* Wp = (mode == 1) ? Wg : (&g_Wc[layer][half * C * C]);

    if (mode == 1 && tid < C) { sv[tid] = g_s[layer][tid]; cv[tid] = g_c[layer][tid]; }
    if (tid < 128) rowss[tid] = 0.f;

    int lr = tid >> 1;              // loader row 0..127
    int kofe = (tid & 1) * 8;       // element sub-offset (floats)
    int kofp = (tid & 1) * 4;       // pair sub-offset
    int gi = i0 + lr;
    float dgl = 0.f;
    if (mode == 1 && gi < NN) dgl = g_deg[gi];
    const float* xr = Xp + (size_t)gi * C;
    const float* wr = Wp + (size_t)lr * C;

    int wid = tid >> 5, lane = tid & 31;
    int gid = lane >> 2, tig = lane & 3;
    int m0 = (wid & 1) * 64, n0 = (wid >> 1) * 32;

    float acc[4][4][4];
#pragma unroll
    for (int a = 0; a < 4; a++)
#pragma unroll
        for (int b = 0; b < 4; b++)
#pragma unroll
            for (int d = 0; d < 4; d++) acc[a][b][d] = 0.f;

    __syncthreads();   // sv/cv/rowss ready

    for (int kc = 0; kc < 8; kc++) {
        int gk = kc * 16 + kofe;
        // --- X chunk (8 floats) with optional affine, split bf16 hi/lo ---
        float xv[8];
        if (gi < NN) {
            float4 v0 = *(const float4*)(xr + gk);
            float4 v1 = *(const float4*)(xr + gk + 4);
            xv[0] = v0.x; xv[1] = v0.y; xv[2] = v0.z; xv[3] = v0.w;
            xv[4] = v1.x; xv[5] = v1.y; xv[6] = v1.z; xv[7] = v1.w;
        } else {
#pragma unroll
            for (int j = 0; j < 8; j++) xv[j] = 0.f;
        }
        if (mode == 1) {
#pragma unroll
            for (int j = 0; j < 8; j++) xv[j] = sv[gk + j] * xv[j] + dgl * cv[gk + j];
        }
#pragma unroll
        for (int j = 0; j < 4; j++) {
            unsigned h, l;
            split2(xv[2 * j], xv[2 * j + 1], h, l);
            AsH[lr * PIT + kofp + j] = h;
            AsL[lr * PIT + kofp + j] = l;
        }
        // --- W chunk ---
        {
            float4 w0 = *(const float4*)(wr + gk);
            float4 w1 = *(const float4*)(wr + gk + 4);
            float wv[8] = {w0.x, w0.y, w0.z, w0.w, w1.x, w1.y, w1.z, w1.w};
#pragma unroll
            for (int j = 0; j < 4; j++) {
                unsigned h, l;
                split2(wv[2 * j], wv[2 * j + 1], h, l);
                WsH[lr * PIT + kofp + j] = h;
                WsL[lr * PIT + kofp + j] = l;
            }
        }
        __syncthreads();

        unsigned bh0[4], bh1[4], bl0[4], bl1[4];
#pragma unroll
        for (int nt = 0; nt < 4; nt++) {
            int n = n0 + nt * 8 + gid;
            bh0[nt] = WsH[n * PIT + tig];
            bh1[nt] = WsH[n * PIT + tig + 4];
            bl0[nt] = WsL[n * PIT + tig];
            bl1[nt] = WsL[n * PIT + tig + 4];
        }
#pragma unroll
        for (int mt = 0; mt < 4; mt++) {
            int m = m0 + mt * 16 + gid;
            unsigned ah0 = AsH[m * PIT + tig];
            unsigned ah1 = AsH[(m + 8) * PIT + tig];
            unsigned ah2 = AsH[m * PIT + tig + 4];
            unsigned ah3 = AsH[(m + 8) * PIT + tig + 4];
            unsigned al0 = AsL[m * PIT + tig];
            unsigned al1 = AsL[(m + 8) * PIT + tig];
            unsigned al2 = AsL[m * PIT + tig + 4];
            unsigned al3 = AsL[(m + 8) * PIT + tig + 4];
#pragma unroll
            for (int nt = 0; nt < 4; nt++) {
                mma16(acc[mt][nt], ah0, ah1, ah2, ah3, bh0[nt], bh1[nt]);
                mma16(acc[mt][nt], ah0, ah1, ah2, ah3, bl0[nt], bl1[nt]);
                mma16(acc[mt][nt], al0, al1, al2, al3, bh0[nt], bh1[nt]);
            }
        }
        __syncthreads();
    }

    // --- epilogue ---
    if (mode == 0) {
        float* outp = half ? g_B : g_A;
#pragma unroll
        for (int mt = 0; mt < 4; mt++) {
            int r0 = i0 + m0 + mt * 16 + gid;
            int r1 = r0 + 8;
#pragma unroll
            for (int nt = 0; nt < 4; nt++) {
                int col = n0 + nt * 8 + 2 * tig;
                float* cc = acc[mt][nt];
                float b0 = 0.f, b1 = 0.f;
                if (half == 0) { b0 = bias[col]; b1 = bias[col + 1]; }
                if (r0 < NN) { float2 v = {cc[0] + b0, cc[1] + b1}; *(float2*)(outp + (size_t)r0 * C + col) = v; }
                if (r1 < NN) { float2 v = {cc[2] + b0, cc[3] + b1}; *(float2*)(outp + (size_t)r1 * C + col) = v; }
            }
        }
    } else if (!do_norm) {
        float* outp = Og;
#pragma unroll
        for (int mt = 0; mt < 4; mt++) {
            int r0 = i0 + m0 + mt * 16 + gid;
            int r1 = r0 + 8;
            float d0 = (r0 < NN) ? g_deg[r0] : 0.f;
            float d1 = (r1 < NN) ? g_deg[r1] : 0.f;
#pragma unroll
            for (int nt = 0; nt < 4; nt++) {
                int col = n0 + nt * 8 + 2 * tig;
                float* cc = acc[mt][nt];
                float bb0 = bias[col], bb1 = bias[col + 1];
                if (r0 < NN) { float2 v = {cc[0] + d0 * bb0, cc[1] + d0 * bb1}; *(float2*)(outp + (size_t)r0 * C + col) = v; }
                if (r1 < NN) { float2 v = {cc[2] + d1 * bb0, cc[3] + d1 * bb1}; *(float2*)(outp + (size_t)r1 * C + col) = v; }
            }
        }
    } else {
        // fused: v = relu(acc + deg*bb); h = v / max(||v||, 1e-12) -> g_H
#pragma unroll
        for (int mt = 0; mt < 4; mt++) {
            int r0 = i0 + m0 + mt * 16 + gid;
            int r1 = r0 + 8;
            int l0 = m0 + mt * 16 + gid, l1 = l0 + 8;
            float d0 = (r0 < NN) ? g_deg[r0] : 0.f;
            float d1 = (r1 < NN) ? g_deg[r1] : 0.f;
            float ss0 = 0.f, ss1 = 0.f;
#pragma unroll
            for (int nt = 0; nt < 4; nt++) {
                int col = n0 + nt * 8 + 2 * tig;
                float* cc = acc[mt][nt];
                float bb0 = bias[col], bb1 = bias[col + 1];
                cc[0] = fmaxf(cc[0] + d0 * bb0, 0.f);
                cc[1] = fmaxf(cc[1] + d0 * bb1, 0.f);
                cc[2] = fmaxf(cc[2] + d1 * bb0, 0.f);
                cc[3] = fmaxf(cc[3] + d1 * bb1, 0.f);
                ss0 += cc[0] * cc[0] + cc[1] * cc[1];
                ss1 += cc[2] * cc[2] + cc[3] * cc[3];
            }
            atomicAdd(&rowss[l0], ss0);
            atomicAdd(&rowss[l1], ss1);
        }
        __syncthreads();
#pragma unroll
        for (int mt = 0; mt < 4; mt++) {
            int r0 = i0 + m0 + mt * 16 + gid;
            int r1 = r0 + 8;
            int l0 = m0 + mt * 16 + gid, l1 = l0 + 8;
            float inv0 = 1.f / fmaxf(sqrtf(rowss[l0]), 1e-12f);
            float inv1 = 1.f / fmaxf(sqrtf(rowss[l1]), 1e-12f);
#pragma unroll
            for (int nt = 0; nt < 4; nt++) {
                int col = n0 + nt * 8 + 2 * tig;
                float* cc = acc[mt][nt];
                if (r0 < NN) { float2 v = {cc[0] * inv0, cc[1] * inv0}; *(float2*)(g_H + (size_t)r0 * C + col) = v; }
                if (r1 < NN) { float2 v = {cc[2] * inv1, cc[3] * inv1}; *(float2*)(g_H + (size_t)r1 * C + col) = v; }
            }
        }
    }
}

// ---------------- CSR edge aggregate: R[i] = sum relu(A[i] + B[src]) -------
__global__ __launch_bounds__(256) void edge_csr_kernel() {
    int node = (blockIdx.x * blockDim.x + threadIdx.x) >> 5;
    int lane = threadIdx.x & 31;
    if (node >= NN) return;
    int s0 = g_rowp[node], s1 = g_rowp[node + 1];
    float4 a = ((const float4*)(g_A + (size_t)node * C))[lane];
    float4 acc = make_float4(0.f, 0.f, 0.f, 0.f);
    int e = s0;
    for (; e + 1 < s1; e += 2) {
        int sa = g_csr[e], sb = g_csr[e + 1];
        float4 b0 = ((const float4*)(g_B + (size_t)sa * C))[lane];
        float4 b1 = ((const float4*)(g_B + (size_t)sb * C))[lane];
        acc.x += fmaxf(a.x + b0.x, 0.f) + fmaxf(a.x + b1.x, 0.f);
        acc.y += fmaxf(a.y + b0.y, 0.f) + fmaxf(a.y + b1.y, 0.f);
        acc.z += fmaxf(a.z + b0.z, 0.f) + fmaxf(a.z + b1.z, 0.f);
        acc.w += fmaxf(a.w + b0.w, 0.f) + fmaxf(a.w + b1.w, 0.f);
    }
    if (e < s1) {
        int sa = g_csr[e];
        float4 b0 = ((const float4*)(g_B + (size_t)sa * C))[lane];
        acc.x += fmaxf(a.x + b0.x, 0.f);
        acc.y += fmaxf(a.y + b0.y, 0.f);
        acc.z += fmaxf(a.z + b0.z, 0.f);
        acc.w += fmaxf(a.w + b0.w, 0.f);
    }
    ((float4*)(g_R + (size_t)node * C))[lane] = acc;
    if (lane == 0) g_deg[node] = (float)(s1 - s0);
}

// ---------------- launch ----------------------------------------------------
extern "C" void kernel_launch(void* const* d_in, const int* in_sizes, int n_in,
                              void* d_out, int out_size) {
    const float* x   = (const float*)d_in[0];
    const void*  ei  = d_in[1];
    const float* w1a = (const float*)d_in[2];
    const float* b1a = (const float*)d_in[3];
    const float* g1  = (const float*)d_in[4];
    const float* be1 = (const float*)d_in[5];
    const float* rm1 = (const float*)d_in[6];
    const float* rv1 = (const float*)d_in[7];
    const float* w1b = (const float*)d_in[8];
    const float* b1b = (const float*)d_in[9];
    const float* w2a = (const float*)d_in[10];
    const float* b2a = (const float*)d_in[11];
    const float* g2  = (const float*)d_in[12];
    const float* be2 = (const float*)d_in[13];
    const float* rm2 = (const float*)d_in[14];
    const float* rv2 = (const float*)d_in[15];
    const float* w2b = (const float*)d_in[16];
    const float* b2b = (const float*)d_in[17];
    float* out = (float*)d_out;

    const int ROWB = (NN + 127) / 128;          // 391
    const int EB   = (NN * 32 + 255) / 256;     // 6250

    prep_all<<<256, 256>>>(w1a, w2a, g1, be1, rm1, rv1, g2, be2, rm2, rv2);
    detect_kernel<<<1, 32>>>(ei);
    convert_hist_kernel<<<(2 * EE + 255) / 256, 256>>>(ei);
    scan_local<<<SCAN_NB, 256>>>();
    scan_bsum<<<1, 256>>>();
    scan_add<<<SCAN_NB, 256>>>();
    scatter_kernel<<<(EE + 255) / 256, 256>>>();

    // ---- layer 1 ----
    mma_gemm<<<dim3(ROWB, 2), 256>>>(x, nullptr, b1a, nullptr, 0, 0, 0, 0);   // -> g_A, g_B
    edge_csr_kernel<<<EB, 256>>>();                                           // -> g_R, g_deg
    mma_gemm<<<dim3(ROWB, 1), 256>>>(nullptr, w1b, b1b, nullptr, 0, 1, 0, 1); // -> g_H (fused norm)

    // ---- layer 2 ----
    mma_gemm<<<dim3(ROWB, 2), 256>>>(nullptr, nullptr, b2a, nullptr, 1, 0, 1, 0); // g_H -> g_A, g_B
    edge_csr_kernel<<<EB, 256>>>();
    mma_gemm<<<dim3(ROWB, 1), 256>>>(nullptr, w2b, b2b, out, 1, 1, 0, 0);     // -> d_out
}